// round 11
// baseline (speedup 1.0000x reference)
#include <cuda_runtime.h>
#include <cstdint>
#include <math.h>

#define D 512
#define K 5
#define TPB 64           // 2 warps per block — fine occupancy granularity
#define NBLOCKS 2048     // 4096 warps -> 16 rows per warp

__global__ __launch_bounds__(TPB, 5) void lfr_pipe3_kernel(
    const float* __restrict__ x,
    const float* __restrict__ alpha,
    const float* __restrict__ classif_w,
    const float* __restrict__ centroids,
    float* __restrict__ out_map,   // (N, K)
    float* __restrict__ out_rec,   // (N, D)
    float* __restrict__ out_pred,  // (N,)
    int n)
{
    const int lane   = threadIdx.x & 31;
    const int gwarp  = (blockIdx.x * TPB + threadIdx.x) >> 5;
    const int nwarps = (gridDim.x * TPB) >> 5;

    // Register caches: lane owns d = (i*32+lane)*4 .. +3, i in 0..3
    float4 a4[4];
    float4 c4[4][K];
#pragma unroll
    for (int i = 0; i < 4; i++) {
        const int d0 = (i * 32 + lane) * 4;
        a4[i] = *(const float4*)(alpha + d0);
#pragma unroll
        for (int k = 0; k < K; k++)
            c4[i][k] = *(const float4*)(centroids + k * D + d0);
    }

    // b[k] = sum_d alpha_d c_kd^2 ; sw[k] = sigmoid(classif_w[k])
    float b[K], sw[K];
#pragma unroll
    for (int k = 0; k < K; k++) {
        float s = 0.f;
#pragma unroll
        for (int i = 0; i < 4; i++) {
            s += a4[i].x * c4[i][k].x * c4[i][k].x
               + a4[i].y * c4[i][k].y * c4[i][k].y
               + a4[i].z * c4[i][k].z * c4[i][k].z
               + a4[i].w * c4[i][k].w * c4[i][k].w;
        }
#pragma unroll
        for (int o = 16; o; o >>= 1) s += __shfl_xor_sync(0xffffffffu, s, o);
        b[k] = s;
        sw[k] = 1.0f / (1.0f + __expf(-classif_w[k]));
    }

    int row = gwarp;
    if (row >= n) return;

    // Depth-3 register pipeline: x0 = current, x1 = +1 stride, x2 = +2 strides
    float4 x0[4], x1[4], x2[4];
    {
        const float4* xr = (const float4*)(x + (size_t)row * D);
#pragma unroll
        for (int i = 0; i < 4; i++) x0[i] = xr[i * 32 + lane];
    }
    if (row + nwarps < n) {
        const float4* xr = (const float4*)(x + (size_t)(row + nwarps) * D);
#pragma unroll
        for (int i = 0; i < 4; i++) x1[i] = xr[i * 32 + lane];
    }
    if (row + 2 * nwarps < n) {
        const float4* xr = (const float4*)(x + (size_t)(row + 2 * nwarps) * D);
#pragma unroll
        for (int i = 0; i < 4; i++) x2[i] = xr[i * 32 + lane];
    }

    while (row < n) {
        // dot_k = sum_d alpha_d x_d c_kd   (consume x0)
        float dot[K];
#pragma unroll
        for (int k = 0; k < K; k++) dot[k] = 0.f;
#pragma unroll
        for (int i = 0; i < 4; i++) {
            const float tx = x0[i].x * a4[i].x;
            const float ty = x0[i].y * a4[i].y;
            const float tz = x0[i].z * a4[i].z;
            const float tw = x0[i].w * a4[i].w;
#pragma unroll
            for (int k = 0; k < K; k++) {
                dot[k] += tx * c4[i][k].x + ty * c4[i][k].y +
                          tz * c4[i][k].z + tw * c4[i][k].w;
            }
        }

        // Rotate pipeline and issue the next load immediately, so it is
        // outstanding through the reduce/softmax/store phase below.
        {
            const int pre = row + 3 * nwarps;
#pragma unroll
            for (int i = 0; i < 4; i++) { x0[i] = x1[i]; x1[i] = x2[i]; }
            if (pre < n) {
                const float4* xr = (const float4*)(x + (size_t)pre * D);
#pragma unroll
                for (int i = 0; i < 4; i++) x2[i] = xr[i * 32 + lane];
            }
        }

        // Butterfly reduce: all lanes get all K dots
#pragma unroll
        for (int k = 0; k < K; k++) {
            float s = dot[k];
#pragma unroll
            for (int o = 16; o; o >>= 1) s += __shfl_xor_sync(0xffffffffu, s, o);
            dot[k] = s;
        }

        // softmax over dist'[k] = b[k] - 2*dot[k] (row-constant term cancels)
        float m[K];
        float mx = -INFINITY;
#pragma unroll
        for (int k = 0; k < K; k++) {
            m[k] = b[k] - 2.0f * dot[k];
            mx = fmaxf(mx, m[k]);
        }
        float sum = 0.f;
#pragma unroll
        for (int k = 0; k < K; k++) { m[k] = __expf(m[k] - mx); sum += m[k]; }
        const float inv = 1.0f / sum;
#pragma unroll
        for (int k = 0; k < K; k++) m[k] *= inv;

        if (lane < K) out_map[(size_t)row * K + lane] = m[lane];
        if (lane == 0) {
            float p = 0.f;
#pragma unroll
            for (int k = 0; k < K; k++) p += m[k] * sw[k];
            out_pred[row] = p;
        }

        // reconstructed = mapping @ centroids (register-resident)
        float4* rr = (float4*)(out_rec + (size_t)row * D);
#pragma unroll
        for (int i = 0; i < 4; i++) {
            float4 r;
            r.x = m[0] * c4[i][0].x; r.y = m[0] * c4[i][0].y;
            r.z = m[0] * c4[i][0].z; r.w = m[0] * c4[i][0].w;
#pragma unroll
            for (int k = 1; k < K; k++) {
                r.x += m[k] * c4[i][k].x;
                r.y += m[k] * c4[i][k].y;
                r.z += m[k] * c4[i][k].z;
                r.w += m[k] * c4[i][k].w;
            }
            rr[i * 32 + lane] = r;
        }

        row += nwarps;
    }
}

extern "C" void kernel_launch(void* const* d_in, const int* in_sizes, int n_in,
                              void* d_out, int out_size) {
    // metadata order: x, is_protected, alpha_p, classif_w, centroids
    const float* x     = (const float*)d_in[0];
    const float* alpha = (const float*)d_in[2];
    const float* cw    = (const float*)d_in[3];
    const float* cent  = (const float*)d_in[4];
    const int n = in_sizes[1];  // N

    float* out      = (float*)d_out;
    float* out_map  = out;                      // N*K
    float* out_rec  = out + (size_t)n * K;      // N*D
    float* out_pred = out_rec + (size_t)n * D;  // N

    lfr_pipe3_kernel<<<NBLOCKS, TPB>>>(x, alpha, cw, cent,
                                       out_map, out_rec, out_pred, n);
}

// round 14
// speedup vs baseline: 1.2518x; 1.2518x over previous
#include <cuda_runtime.h>
#include <cstdint>
#include <math.h>

#define D 512
#define K 5
#define TPB 128          // 4 warps per block (R4 topology — best measured)
#define NBLOCKS 4096     // 16384 warps -> 4 rows per warp

__device__ __forceinline__ void prefetch_l2(const void* p) {
    asm volatile("prefetch.global.L2 [%0];" :: "l"(p));
}

__global__ __launch_bounds__(TPB) void lfr_pf_kernel(
    const float* __restrict__ x,
    const float* __restrict__ alpha,
    const float* __restrict__ classif_w,
    const float* __restrict__ centroids,
    float* __restrict__ out_map,   // (N, K)
    float* __restrict__ out_rec,   // (N, D)
    float* __restrict__ out_pred,  // (N,)
    int n)
{
    const int lane   = threadIdx.x & 31;
    const int gwarp  = (blockIdx.x * TPB + threadIdx.x) >> 5;
    const int nwarps = (gridDim.x * TPB) >> 5;

    // Register caches: lane owns d = (i*32+lane)*4 .. +3, i in 0..3
    float4 a4[4];
    float4 c4[4][K];
#pragma unroll
    for (int i = 0; i < 4; i++) {
        const int d0 = (i * 32 + lane) * 4;
        a4[i] = *(const float4*)(alpha + d0);
#pragma unroll
        for (int k = 0; k < K; k++)
            c4[i][k] = *(const float4*)(centroids + k * D + d0);
    }

    // b[k] = sum_d alpha_d c_kd^2 ; sw[k] = sigmoid(classif_w[k])
    float b[K], sw[K];
#pragma unroll
    for (int k = 0; k < K; k++) {
        float s = 0.f;
#pragma unroll
        for (int i = 0; i < 4; i++) {
            s += a4[i].x * c4[i][k].x * c4[i][k].x
               + a4[i].y * c4[i][k].y * c4[i][k].y
               + a4[i].z * c4[i][k].z * c4[i][k].z
               + a4[i].w * c4[i][k].w * c4[i][k].w;
        }
#pragma unroll
        for (int o = 16; o; o >>= 1) s += __shfl_xor_sync(0xffffffffu, s, o);
        b[k] = s;
        sw[k] = 1.0f / (1.0f + __expf(-classif_w[k]));
    }

    int row = gwarp;
    if (row >= n) return;

    // Prime: load row, L2-prefetch row+stride (full 2KB row: 16 lanes x 128B)
    float4 xv[4];
    {
        const float4* xr = (const float4*)(x + (size_t)row * D);
#pragma unroll
        for (int i = 0; i < 4; i++) xv[i] = __ldcs(&xr[i * 32 + lane]);
    }
    if (row + nwarps < n && lane < 16)
        prefetch_l2(x + (size_t)(row + nwarps) * D + lane * 32);

    for (; row < n; ) {
        const int next = row + nwarps;

        // L2-prefetch two rows ahead (no registers consumed; DRAM leg runs
        // off the prefetch queue so the architectural load below hits L2)
        if (next + nwarps < n && lane < 16)
            prefetch_l2(x + (size_t)(next + nwarps) * D + lane * 32);

        // Architectural load of next row (should be L2-resident)
        float4 xn[4];
        if (next < n) {
            const float4* xr = (const float4*)(x + (size_t)next * D);
#pragma unroll
            for (int i = 0; i < 4; i++) xn[i] = __ldcs(&xr[i * 32 + lane]);
        }

        // dot_k = sum_d alpha_d x_d c_kd (per-lane partials)
        float dot[K];
#pragma unroll
        for (int k = 0; k < K; k++) dot[k] = 0.f;
#pragma unroll
        for (int i = 0; i < 4; i++) {
            const float tx = xv[i].x * a4[i].x;
            const float ty = xv[i].y * a4[i].y;
            const float tz = xv[i].z * a4[i].z;
            const float tw = xv[i].w * a4[i].w;
#pragma unroll
            for (int k = 0; k < K; k++) {
                dot[k] += tx * c4[i][k].x + ty * c4[i][k].y +
                          tz * c4[i][k].z + tw * c4[i][k].w;
            }
        }
        // Butterfly reduce: all lanes end with all K dots
#pragma unroll
        for (int k = 0; k < K; k++) {
            float s = dot[k];
#pragma unroll
            for (int o = 16; o; o >>= 1) s += __shfl_xor_sync(0xffffffffu, s, o);
            dot[k] = s;
        }

        // softmax over dist'[k] = b[k] - 2*dot[k] (row-constant term cancels)
        float m[K];
        float mx = -INFINITY;
#pragma unroll
        for (int k = 0; k < K; k++) {
            m[k] = b[k] - 2.0f * dot[k];
            mx = fmaxf(mx, m[k]);
        }
        float sum = 0.f;
#pragma unroll
        for (int k = 0; k < K; k++) { m[k] = __expf(m[k] - mx); sum += m[k]; }
        const float inv = 1.0f / sum;
#pragma unroll
        for (int k = 0; k < K; k++) m[k] *= inv;

        if (lane < K) out_map[(size_t)row * K + lane] = m[lane];
        if (lane == 0) {
            float p = 0.f;
#pragma unroll
            for (int k = 0; k < K; k++) p += m[k] * sw[k];
            out_pred[row] = p;
        }

        // reconstructed = mapping @ centroids (register-resident), streaming
        float4* rr = (float4*)(out_rec + (size_t)row * D);
#pragma unroll
        for (int i = 0; i < 4; i++) {
            float4 r;
            r.x = m[0] * c4[i][0].x; r.y = m[0] * c4[i][0].y;
            r.z = m[0] * c4[i][0].z; r.w = m[0] * c4[i][0].w;
#pragma unroll
            for (int k = 1; k < K; k++) {
                r.x += m[k] * c4[i][k].x;
                r.y += m[k] * c4[i][k].y;
                r.z += m[k] * c4[i][k].z;
                r.w += m[k] * c4[i][k].w;
            }
            __stcs(&rr[i * 32 + lane], r);
        }

        row = next;
#pragma unroll
        for (int i = 0; i < 4; i++) xv[i] = xn[i];
    }
}

extern "C" void kernel_launch(void* const* d_in, const int* in_sizes, int n_in,
                              void* d_out, int out_size) {
    // metadata order: x, is_protected, alpha_p, classif_w, centroids
    const float* x     = (const float*)d_in[0];
    const float* alpha = (const float*)d_in[2];
    const float* cw    = (const float*)d_in[3];
    const float* cent  = (const float*)d_in[4];
    const int n = in_sizes[1];  // N

    float* out      = (float*)d_out;
    float* out_map  = out;                      // N*K
    float* out_rec  = out + (size_t)n * K;      // N*D
    float* out_pred = out_rec + (size_t)n * D;  // N

    lfr_pf_kernel<<<NBLOCKS, TPB>>>(x, alpha, cw, cent,
                                    out_map, out_rec, out_pred, n);
}